// round 8
// baseline (speedup 1.0000x reference)
#include <cuda_runtime.h>
#include <cstdint>

// Problem constants
#define NSEG 6
#define NCH  512
#define NPOS 16384     // 128*128
#define NBINS 16
#define NBLK 592       // 4 blocks/SM x 148 SMs; residency guaranteed by launch_bounds

// ---------------- device scratch (no allocation allowed) ----------------
__device__ float    g_fm[NSEG * NPOS];       // float 0/1 mask per position
__device__ int      g_posA[NSEG * NBINS];    // bin window start (position)
__device__ int      g_posB[NSEG * NBINS];    // bin window end (exclusive)
__device__ float    g_rdenom[NSEG * NBINS];  // 1/denom per bin
__device__ float    g_ys[NSEG * NCH * NBINS];
__device__ float    g_h1p[4][NSEG * 2048];   // fcA partials (K-split 4)
__device__ float    g_h2p[2][NSEG * 512];    // fcB partials (K-split 2)
__device__ float    g_w0[NSEG * 512];
__device__ unsigned          g_count;        // barrier arrivals (self-resetting)
__device__ volatile unsigned g_gen;          // barrier generation (monotonic across replays)

// ---------------- helpers ----------------
__device__ __forceinline__ void ffma2(unsigned long long& acc,
                                      unsigned long long v,
                                      unsigned long long m)
{
    asm("fma.rn.f32x2 %0, %1, %2, %0;" : "+l"(acc) : "l"(v), "l"(m));
}
#define ULL(f4part) (*(const unsigned long long*)&(f4part))

__device__ __forceinline__ float dot4(float4 a, float4 b, float acc)
{
    acc = fmaf(a.x, b.x, acc);
    acc = fmaf(a.y, b.y, acc);
    acc = fmaf(a.z, b.z, acc);
    acc = fmaf(a.w, b.w, acc);
    return acc;
}
__device__ __forceinline__ float4 add4(float4 a, float4 b)
{ return make_float4(a.x + b.x, a.y + b.y, a.z + b.z, a.w + b.w); }

__device__ __forceinline__ float warp_red(float a)
{
#pragma unroll
    for (int o = 16; o; o >>= 1) a += __shfl_xor_sync(0xffffffffu, a, o);
    return a;
}

// Grid-wide barrier: all blocks resident (guaranteed by launch_bounds + NBLK).
__device__ __forceinline__ void grid_barrier()
{
    __syncthreads();
    __threadfence();
    if (threadIdx.x == 0) {
        unsigned gen = g_gen;
        if (atomicAdd(&g_count, 1u) == gridDim.x - 1) {
            g_count = 0;
            __threadfence();
            g_gen = gen + 1;            // release
        } else {
            int backoff = 32;
            while (g_gen == gen) {
                __nanosleep(backoff);
                if (backoff < 256) backoff <<= 1;
            }
        }
        __threadfence();                // acquire
    }
    __syncthreads();
}

// ---------------- the megakernel ----------------
__global__ void __launch_bounds__(256, 4) k_mega(
    const float* __restrict__ xs,      const int* __restrict__ parsing,
    const float* __restrict__ fcA_w,   const float* __restrict__ fcA_b,
    const float* __restrict__ fcB_w,   const float* __restrict__ fcB_b,
    const float* __restrict__ fcC_w,   const float* __restrict__ fcC_b,
    const float* __restrict__ p1w, const float* __restrict__ p1b,
    const float* __restrict__ p2w, const float* __restrict__ p2b,
    const float* __restrict__ p3w, const float* __restrict__ p3b,
    float* __restrict__ out)
{
    __shared__ __align__(16) char smraw[8448];
    const int tid  = threadIdx.x;
    const int wid  = tid >> 5;
    const int lane = tid & 31;

    // ================= P0: prep (blocks 0..5) =================
    if (blockIdx.x < NSEG) {
        const int s = blockIdx.x;
        int* ssum   = (int*)smraw;           // 256 ints
        int* sstart = ssum + 256;            // 16
        int* send   = sstart + 16;           // 16

        const int4* __restrict__ pv = (const int4*)(parsing + s * 65536);
        const int base = tid * 64;           // 64 positions, same h row (w0 in {0,64})
        const int h  = base >> 7;
        const int w0 = base & 127;

        int cnt = 0;
        unsigned mw0 = 0, mw1 = 0;
#pragma unroll
        for (int j = 0; j < 64; j += 2) {
            int w = w0 + j;
            int4 v = pv[h * 128 + (w >> 1)];
            unsigned m0 = (v.x != 0), m1 = (v.z != 0);
            cnt += (int)(m0 + m1);
            if (j < 32) { mw0 |= m0 << j;        mw0 |= m1 << (j + 1); }
            else        { mw1 |= m0 << (j - 32); mw1 |= m1 << (j - 31); }
        }

        // float 0/1 mask, 16 float4 stores (256B contiguous per thread)
        {
            float4* fmv = (float4*)(g_fm + s * NPOS + base);
#pragma unroll
            for (int q = 0; q < 16; q++) {
                unsigned mm = (q < 8) ? mw0 : mw1;
                int qq = (q & 7) << 2;
                float4 f;
                f.x = ((mm >> qq)       & 1u) ? 1.f : 0.f;
                f.y = ((mm >> (qq + 1)) & 1u) ? 1.f : 0.f;
                f.z = ((mm >> (qq + 2)) & 1u) ? 1.f : 0.f;
                f.w = ((mm >> (qq + 3)) & 1u) ? 1.f : 0.f;
                fmv[q] = f;
            }
        }

        ssum[tid] = cnt;
        __syncthreads();
        for (int off = 1; off < 256; off <<= 1) {
            int v = (tid >= off) ? ssum[tid - off] : 0;
            __syncthreads();
            ssum[tid] += v;
            __syncthreads();
        }
        const int incl = ssum[tid];
        const int L    = ssum[255];
        const int exc  = incl - cnt;

        if (tid < NBINS) {
            int k  = tid;
            int st = (k * L) >> 4;
            int en = ((k + 1) * L + 15) >> 4;
            sstart[k] = st;
            send[k]   = en;
            int d = en - st; if (d < 1) d = 1;
            g_rdenom[s * NBINS + k] = 1.0f / (float)d;
            g_posA[s * NBINS + k] = 0;
            g_posB[s * NBINS + k] = 0;
        }
        __syncthreads();

        int r = exc;
#pragma unroll 1
        for (int j = 0; j < 64; j++) {
            unsigned bit = (j < 32) ? ((mw0 >> j) & 1u) : ((mw1 >> (j - 32)) & 1u);
            if (bit) {
                int p = base + j;
                for (int k = 0; k < NBINS; k++) {
                    if (r == sstart[k])   g_posA[s * NBINS + k] = p;
                    if (r + 1 == send[k]) g_posB[s * NBINS + k] = p + 1;
                }
                r++;
            }
        }
    }
    grid_barrier();

    // ================= P1: pool (3072 tiles, 8 bins/block, 2 ch/warp) ====
    for (int t = blockIdx.x; t < NSEG * 512; t += NBLK) {
        const int s    = t >> 9;
        const int rem  = t & 511;
        const int cp   = rem >> 1;
        const int half = rem & 1;
        const int bin  = half * 8 + wid;
        const int c0   = cp * 2;

        const int lo = g_posA[s * NBINS + bin];
        const int hi = g_posB[s * NBINS + bin];

        const size_t chbase = ((size_t)(s * NCH + c0)) << 14;
        const float4* __restrict__ xa4 = (const float4*)(xs + chbase);
        const float4* __restrict__ xb4 = xa4 + (NPOS >> 2);
        const float4* __restrict__ fm4 = (const float4*)(g_fm + s * NPOS);

        const int ilo2 = (lo + 3) >> 2;
        const int ihi2 = hi >> 2;

        unsigned long long accA = 0, accB = 0;
        float eA = 0.f, eB = 0.f;

        int i = ilo2 + lane;
        for (; i + 32 < ihi2; i += 64) {
            float4 f0 = fm4[i];
            float4 a0 = xa4[i];
            float4 b0 = xb4[i];
            float4 f1 = fm4[i + 32];
            float4 a1 = xa4[i + 32];
            float4 b1 = xb4[i + 32];
            ffma2(accA, ULL(a0.x), ULL(f0.x));
            ffma2(accA, ULL(a0.z), ULL(f0.z));
            ffma2(accB, ULL(b0.x), ULL(f0.x));
            ffma2(accB, ULL(b0.z), ULL(f0.z));
            ffma2(accA, ULL(a1.x), ULL(f1.x));
            ffma2(accA, ULL(a1.z), ULL(f1.z));
            ffma2(accB, ULL(b1.x), ULL(f1.x));
            ffma2(accB, ULL(b1.z), ULL(f1.z));
        }
        if (i < ihi2) {
            float4 f0 = fm4[i];
            float4 a0 = xa4[i];
            float4 b0 = xb4[i];
            ffma2(accA, ULL(a0.x), ULL(f0.x));
            ffma2(accA, ULL(a0.z), ULL(f0.z));
            ffma2(accB, ULL(b0.x), ULL(f0.x));
            ffma2(accB, ULL(b0.z), ULL(f0.z));
        }

        if (lane == 0) {
            for (int e = (lo >> 2); e < ilo2; e++) {
                float4 fa = fm4[e];
                float4 va = xa4[e];
                float4 vb = xb4[e];
                int p = e << 2;
                float m0 = (p     >= lo && p     < hi) ? fa.x : 0.f;
                float m1 = (p + 1 >= lo && p + 1 < hi) ? fa.y : 0.f;
                float m2 = (p + 2 >= lo && p + 2 < hi) ? fa.z : 0.f;
                float m3 = (p + 3 >= lo && p + 3 < hi) ? fa.w : 0.f;
                eA += va.x * m0 + va.y * m1 + va.z * m2 + va.w * m3;
                eB += vb.x * m0 + vb.y * m1 + vb.z * m2 + vb.w * m3;
            }
        }
        if (lane == 1) {
            int e0 = (ihi2 > ilo2) ? ihi2 : ilo2;
            for (int e = e0; e < ((hi + 3) >> 2); e++) {
                float4 fa = fm4[e];
                float4 va = xa4[e];
                float4 vb = xb4[e];
                int p = e << 2;
                float m0 = (p     >= lo && p     < hi) ? fa.x : 0.f;
                float m1 = (p + 1 >= lo && p + 1 < hi) ? fa.y : 0.f;
                float m2 = (p + 2 >= lo && p + 2 < hi) ? fa.z : 0.f;
                float m3 = (p + 3 >= lo && p + 3 < hi) ? fa.w : 0.f;
                eA += va.x * m0 + va.y * m1 + va.z * m2 + va.w * m3;
                eB += vb.x * m0 + vb.y * m1 + vb.z * m2 + vb.w * m3;
            }
        }

        float2 a2 = *(float2*)&accA;
        float2 b2 = *(float2*)&accB;
        float accAf = a2.x + a2.y + eA;
        float accBf = b2.x + b2.y + eB;
#pragma unroll
        for (int o = 16; o; o >>= 1) {
            accAf += __shfl_xor_sync(0xffffffffu, accAf, o);
            accBf += __shfl_xor_sync(0xffffffffu, accBf, o);
        }
        if (lane == 0) {
            float rd = g_rdenom[s * NBINS + bin];
            g_ys[s * (NCH * NBINS) + c0 * NBINS + bin]       = accAf * rd;
            g_ys[s * (NCH * NBINS) + (c0 + 1) * NBINS + bin] = accBf * rd;
        }
    }
    grid_barrier();

    // ================= P2: fcA (6144 tiles, K-split 4) =================
    for (int t = blockIdx.x; t < 6144; t += NBLK) {
        float4* sx = (float4*)smraw;           // 512 float4 = 2048 floats
        const int s     = t >> 10;
        const int rem   = t & 1023;
        const int chunk = rem >> 8;
        const int row   = (rem & 255) * 8 + wid;

        __syncthreads();                       // previous tile readers done
        const float4* __restrict__ xv = (const float4*)(g_ys + s * 8192 + chunk * 2048);
        for (int i = tid; i < 512; i += 256) sx[i] = xv[i];
        __syncthreads();

        const float4* __restrict__ wv =
            (const float4*)(fcA_w + (size_t)(s * 2048 + row) * 8192 + chunk * 2048);

        float a0 = 0.f, a1 = 0.f, a2 = 0.f, a3 = 0.f;
#pragma unroll 1
        for (int u = 0; u < 4; u++) {
            const int b = u * 128 + lane;
            float4 w0 = wv[b], w1 = wv[b + 32], w2 = wv[b + 64], w3 = wv[b + 96];
            a0 = dot4(w0, sx[b], a0);
            a1 = dot4(w1, sx[b + 32], a1);
            a2 = dot4(w2, sx[b + 64], a2);
            a3 = dot4(w3, sx[b + 96], a3);
        }
        float a = warp_red((a0 + a1) + (a2 + a3));
        if (lane == 0) g_h1p[chunk][s * 2048 + row] = a;
    }
    grid_barrier();

    // ================= P3: fcB (768 tiles, K-split 2) =================
    for (int t = blockIdx.x; t < 768; t += NBLK) {
        float4* sx = (float4*)smraw;           // 256 float4
        const int s     = t >> 7;
        const int rem   = t & 127;
        const int chunk = rem >> 6;
        const int row   = (rem & 63) * 8 + wid;

        const int xoff = (s * 2048 + chunk * 1024) >> 2;
        __syncthreads();
        {
            const float4* q0 = ((const float4*)g_h1p[0]) + xoff;
            const float4* q1 = ((const float4*)g_h1p[1]) + xoff;
            const float4* q2 = ((const float4*)g_h1p[2]) + xoff;
            const float4* q3 = ((const float4*)g_h1p[3]) + xoff;
            const float4* bb = ((const float4*)fcA_b) + xoff;
            for (int i = tid; i < 256; i += 256)
                sx[i] = add4(add4(add4(q0[i], q1[i]), add4(q2[i], q3[i])), bb[i]);
        }
        __syncthreads();

        const float4* __restrict__ wv =
            (const float4*)(fcB_w + (size_t)(s * 512 + row) * 2048 + chunk * 1024);

        float a0 = 0.f, a1 = 0.f, a2 = 0.f, a3 = 0.f;
#pragma unroll 1
        for (int u = 0; u < 2; u++) {
            const int b = u * 128 + lane;
            float4 w0 = wv[b], w1 = wv[b + 32], w2 = wv[b + 64], w3 = wv[b + 96];
            a0 = dot4(w0, sx[b], a0);
            a1 = dot4(w1, sx[b + 32], a1);
            a2 = dot4(w2, sx[b + 64], a2);
            a3 = dot4(w3, sx[b + 96], a3);
        }
        float a = warp_red((a0 + a1) + (a2 + a3));
        if (lane == 0) g_h2p[chunk][s * 512 + row] = a;
    }
    grid_barrier();

    // ================= P4: fcC (384 tiles) =================
    for (int t = blockIdx.x; t < 384; t += NBLK) {
        float4* sx = (float4*)smraw;           // 128 float4
        const int s   = t >> 6;
        const int row = (t & 63) * 8 + wid;

        __syncthreads();
        {
            const int xoff = (s * 512) >> 2;
            const float4* q0 = ((const float4*)g_h2p[0]) + xoff;
            const float4* q1 = ((const float4*)g_h2p[1]) + xoff;
            const float4* bb = ((const float4*)fcB_b) + xoff;
            if (tid < 128)
                sx[tid] = add4(add4(q0[tid], q1[tid]), bb[tid]);
        }
        __syncthreads();

        const float4* __restrict__ wv = (const float4*)(fcC_w + (size_t)(s * 512 + row) * 512);
        float a0 = dot4(wv[lane],      sx[lane],      0.f);
        float a1 = dot4(wv[lane + 32], sx[lane + 32], 0.f);
        float a2 = dot4(wv[lane + 64], sx[lane + 64], 0.f);
        float a3 = dot4(wv[lane + 96], sx[lane + 96], 0.f);
        float a = warp_red((a0 + a1) + (a2 + a3));
        if (lane == 0) {
            float r = a + fcC_b[s * 512 + row];
            g_w0[s * 512 + row] = r;
            out[s * 960 + row]  = r;
        }
    }
    grid_barrier();

    // ================= P5: tail p1->p2->p3 (blocks 0..5) =================
    if (blockIdx.x < NSEG) {
        const int s = blockIdx.x;
        float* sw0 = (float*)smraw;            // 512
        float* sw1 = sw0 + 512;                // 256
        float* sw2 = sw1 + 256;                // 128

        for (int i = tid; i < 512; i += 256) sw0[i] = g_w0[s * 512 + i];
        __syncthreads();

        // p1: 256 rows, K=512
        for (int row = wid; row < 256; row += 8) {
            const float4* wr = (const float4*)(p1w + (size_t)row * 512);
            const float4* xr = (const float4*)sw0;
            float a = 0.f;
            for (int i = lane; i < 128; i += 32) a = dot4(wr[i], xr[i], a);
            a = warp_red(a);
            if (lane == 0) {
                float r = a + p1b[row];
                sw1[row] = r;
                out[s * 960 + 512 + row] = r;
            }
        }
        __syncthreads();
        // p2: 128 rows, K=256
        for (int row = wid; row < 128; row += 8) {
            const float4* wr = (const float4*)(p2w + (size_t)row * 256);
            const float4* xr = (const float4*)sw1;
            float a = 0.f;
            for (int i = lane; i < 64; i += 32) a = dot4(wr[i], xr[i], a);
            a = warp_red(a);
            if (lane == 0) {
                float r = a + p2b[row];
                sw2[row] = r;
                out[s * 960 + 768 + row] = r;
            }
        }
        __syncthreads();
        // p3: 64 rows, K=128
        for (int row = wid; row < 64; row += 8) {
            const float4* wr = (const float4*)(p3w + (size_t)row * 128);
            const float4* xr = (const float4*)sw2;
            float a = 0.f;
            for (int i = lane; i < 32; i += 32) a = dot4(wr[i], xr[i], a);
            a = warp_red(a);
            if (lane == 0) out[s * 960 + 896 + row] = a + p3b[row];
        }
    }
}

// ---------------- launch ----------------
extern "C" void kernel_launch(void* const* d_in, const int* in_sizes, int n_in,
                              void* d_out, int out_size)
{
    const float* xs      = (const float*)d_in[0];
    const int*   parsing = (const int*)  d_in[1];
    const float* fcA_w   = (const float*)d_in[2];
    const float* fcA_b   = (const float*)d_in[3];
    const float* fcB_w   = (const float*)d_in[4];
    const float* fcB_b   = (const float*)d_in[5];
    const float* fcC_w   = (const float*)d_in[6];
    const float* fcC_b   = (const float*)d_in[7];
    const float* p1_w    = (const float*)d_in[8];
    const float* p1_b    = (const float*)d_in[9];
    const float* p2_w    = (const float*)d_in[10];
    const float* p2_b    = (const float*)d_in[11];
    const float* p3_w    = (const float*)d_in[12];
    const float* p3_b    = (const float*)d_in[13];
    float* out = (float*)d_out;

    k_mega<<<NBLK, 256>>>(xs, parsing, fcA_w, fcA_b, fcB_w, fcB_b,
                          fcC_w, fcC_b, p1_w, p1_b, p2_w, p2_b, p3_w, p3_b, out);
}

// round 10
// speedup vs baseline: 1.5158x; 1.5158x over previous
#include <cuda_runtime.h>
#include <cstdint>

// Problem constants
#define NSEG 6
#define NCH  512
#define NPOS 16384     // 128*128
#define NBINS 16

// ---------------- device scratch (no allocation allowed) ----------------
__device__ unsigned g_mbits[NSEG * 512];     // bit-packed mask, 512 u32/segment
__device__ float    g_fm[NSEG * NPOS];       // float 0/1 mask per position
__device__ int      g_posA[NSEG * NBINS];    // bin window start (position)
__device__ int      g_posB[NSEG * NBINS];    // bin window end (exclusive)
__device__ float    g_rdenom[NSEG * NBINS];  // 1/denom per bin
__device__ float    g_ys[NSEG * NCH * NBINS];
__device__ float    g_h1p[4][NSEG * 2048];   // fcA partials (K-split 4)
__device__ float    g_h2p[2][NSEG * 512];    // fcB partials (K-split 2)
__device__ float    g_w0[NSEG * 512];

// ---------------- K0: mask build (12 blocks x 256 = 3072 threads) --------
// One thread per mbits word: 6 segments x 512 words, 32 positions each.
__global__ void __launch_bounds__(256) k_mask(const int* __restrict__ parsing)
{
    const int gtid = blockIdx.x * 256 + threadIdx.x;     // 0..3071
    const int s    = gtid >> 9;                           // / 512  -> 0..5
    const int tseg = gtid & 511;                          // 0..511
    const int base = tseg * 32;                           // 32 positions, same row

    const int4* __restrict__ pv = (const int4*)(parsing + s * 65536);
    const int h  = base >> 7;
    const int w0 = base & 127;

    unsigned mw = 0;
#pragma unroll
    for (int j = 0; j < 32; j += 2) {
        int w = w0 + j;
        int4 v = pv[h * 128 + (w >> 1)];
        unsigned m0 = (v.x != 0), m1 = (v.z != 0);
        mw |= m0 << j;
        mw |= m1 << (j + 1);
    }
    g_mbits[s * 512 + tseg] = mw;

    float4* fmv = (float4*)(g_fm + s * NPOS + base);
#pragma unroll
    for (int q = 0; q < 8; q++) {
        int qq = q << 2;
        float4 f;
        f.x = ((mw >> qq)       & 1u) ? 1.f : 0.f;
        f.y = ((mw >> (qq + 1)) & 1u) ? 1.f : 0.f;
        f.z = ((mw >> (qq + 2)) & 1u) ? 1.f : 0.f;
        f.w = ((mw >> (qq + 3)) & 1u) ? 1.f : 0.f;
        fmv[q] = f;
    }
}

// ---------------- K1: scan + bin boundaries (reads mbits only) ----------
__global__ void __launch_bounds__(512) k_bins()
{
    const int s = blockIdx.x;
    const int tid = threadIdx.x;
    __shared__ int ssum[512];
    __shared__ int sstart[NBINS], send[NBINS];

    const unsigned mw = g_mbits[s * 512 + tid];
    const int cnt = __popc(mw);
    const int base = tid * 32;

    ssum[tid] = cnt;
    __syncthreads();
    for (int off = 1; off < 512; off <<= 1) {
        int v = (tid >= off) ? ssum[tid - off] : 0;
        __syncthreads();
        ssum[tid] += v;
        __syncthreads();
    }
    const int incl = ssum[tid];
    const int L    = ssum[511];
    const int exc  = incl - cnt;

    if (tid < NBINS) {
        int k  = tid;
        int st = (k * L) >> 4;
        int en = ((k + 1) * L + 15) >> 4;
        sstart[k] = st;
        send[k]   = en;
        int d = en - st; if (d < 1) d = 1;
        g_rdenom[s * NBINS + k] = 1.0f / (float)d;
        g_posA[s * NBINS + k] = 0;
        g_posB[s * NBINS + k] = 0;
    }
    __syncthreads();

    int r = exc;
#pragma unroll 1
    for (int j = 0; j < 32; j++) {
        if ((mw >> j) & 1u) {
            int p = base + j;
            for (int k = 0; k < NBINS; k++) {
                if (r == sstart[k])   g_posA[s * NBINS + k] = p;
                if (r + 1 == send[k]) g_posB[s * NBINS + k] = p + 1;
            }
            r++;
        }
    }
}

// ---------------- packed f32x2 FMA ----------------
__device__ __forceinline__ void ffma2(unsigned long long& acc,
                                      unsigned long long v,
                                      unsigned long long m)
{
    asm("fma.rn.f32x2 %0, %1, %2, %0;" : "+l"(acc) : "l"(v), "l"(m));
}
#define ULL(f4part) (*(const unsigned long long*)&(f4part))

// ---------------- K2: masked adaptive pool, 4 channels / warp ------------
// grid = NSEG * 128 blocks (channel quads), 512 threads = 16 warps (bin each).
__global__ void __launch_bounds__(512, 2) k_pool(const float* __restrict__ xs)
{
    const int bid  = blockIdx.x;          // s*128 + cq
    const int s    = bid >> 7;
    const int cq   = bid & 127;
    const int c0   = cq * 4;
    const int warp = threadIdx.x >> 5;
    const int lane = threadIdx.x & 31;

    const int lo = g_posA[s * NBINS + warp];
    const int hi = g_posB[s * NBINS + warp];

    const size_t chbase = ((size_t)(s * NCH + c0)) << 14;
    const float4* __restrict__ xa4 = (const float4*)(xs + chbase);
    const float4* __restrict__ xb4 = xa4 + (NPOS >> 2);
    const float4* __restrict__ xc4 = xb4 + (NPOS >> 2);
    const float4* __restrict__ xd4 = xc4 + (NPOS >> 2);
    const float4* __restrict__ fm4 = (const float4*)(g_fm + s * NPOS);

    const int ilo2 = (lo + 3) >> 2;       // first fully-inside float4
    const int ihi2 = hi >> 2;             // end of fully-inside float4s

    unsigned long long accA = 0, accB = 0, accC = 0, accD = 0;
    float eA = 0.f, eB = 0.f, eC = 0.f, eD = 0.f;

    for (int i = ilo2 + lane; i < ihi2; i += 32) {
        float4 f0 = fm4[i];
        float4 a0 = xa4[i];
        float4 b0 = xb4[i];
        float4 c0v = xc4[i];
        float4 d0 = xd4[i];
        ffma2(accA, ULL(a0.x), ULL(f0.x));
        ffma2(accA, ULL(a0.z), ULL(f0.z));
        ffma2(accB, ULL(b0.x), ULL(f0.x));
        ffma2(accB, ULL(b0.z), ULL(f0.z));
        ffma2(accC, ULL(c0v.x), ULL(f0.x));
        ffma2(accC, ULL(c0v.z), ULL(f0.z));
        ffma2(accD, ULL(d0.x), ULL(f0.x));
        ffma2(accD, ULL(d0.z), ULL(f0.z));
    }

    // edge float4s (≤1 each side) with explicit window checks
    if (lane == 0) {
        for (int e = (lo >> 2); e < ilo2; e++) {
            float4 fa = fm4[e];
            float4 va = xa4[e];
            float4 vb = xb4[e];
            float4 vc = xc4[e];
            float4 vd = xd4[e];
            int p = e << 2;
            float m0 = (p     >= lo && p     < hi) ? fa.x : 0.f;
            float m1 = (p + 1 >= lo && p + 1 < hi) ? fa.y : 0.f;
            float m2 = (p + 2 >= lo && p + 2 < hi) ? fa.z : 0.f;
            float m3 = (p + 3 >= lo && p + 3 < hi) ? fa.w : 0.f;
            eA += va.x * m0 + va.y * m1 + va.z * m2 + va.w * m3;
            eB += vb.x * m0 + vb.y * m1 + vb.z * m2 + vb.w * m3;
            eC += vc.x * m0 + vc.y * m1 + vc.z * m2 + vc.w * m3;
            eD += vd.x * m0 + vd.y * m1 + vd.z * m2 + vd.w * m3;
        }
    }
    if (lane == 1) {
        int e0 = (ihi2 > ilo2) ? ihi2 : ilo2;
        for (int e = e0; e < ((hi + 3) >> 2); e++) {
            float4 fa = fm4[e];
            float4 va = xa4[e];
            float4 vb = xb4[e];
            float4 vc = xc4[e];
            float4 vd = xd4[e];
            int p = e << 2;
            float m0 = (p     >= lo && p     < hi) ? fa.x : 0.f;
            float m1 = (p + 1 >= lo && p + 1 < hi) ? fa.y : 0.f;
            float m2 = (p + 2 >= lo && p + 2 < hi) ? fa.z : 0.f;
            float m3 = (p + 3 >= lo && p + 3 < hi) ? fa.w : 0.f;
            eA += va.x * m0 + va.y * m1 + va.z * m2 + va.w * m3;
            eB += vb.x * m0 + vb.y * m1 + vb.z * m2 + vb.w * m3;
            eC += vc.x * m0 + vc.y * m1 + vc.z * m2 + vc.w * m3;
            eD += vd.x * m0 + vd.y * m1 + vd.z * m2 + vd.w * m3;
        }
    }

    float2 a2 = *(float2*)&accA;
    float2 b2 = *(float2*)&accB;
    float2 c2 = *(float2*)&accC;
    float2 d2 = *(float2*)&accD;
    float rA = a2.x + a2.y + eA;
    float rB = b2.x + b2.y + eB;
    float rC = c2.x + c2.y + eC;
    float rD = d2.x + d2.y + eD;
#pragma unroll
    for (int o = 16; o; o >>= 1) {
        rA += __shfl_xor_sync(0xffffffffu, rA, o);
        rB += __shfl_xor_sync(0xffffffffu, rB, o);
        rC += __shfl_xor_sync(0xffffffffu, rC, o);
        rD += __shfl_xor_sync(0xffffffffu, rD, o);
    }
    if (lane == 0) {
        float rd = g_rdenom[s * NBINS + warp];
        float* yb = g_ys + s * (NCH * NBINS) + c0 * NBINS + warp;
        yb[0]         = rA * rd;
        yb[NBINS]     = rB * rd;
        yb[2 * NBINS] = rC * rd;
        yb[3 * NBINS] = rD * rd;
    }
}

// ---------------- helpers ----------------
__device__ __forceinline__ float dot4(float4 a, float4 b, float acc)
{
    acc = fmaf(a.x, b.x, acc);
    acc = fmaf(a.y, b.y, acc);
    acc = fmaf(a.z, b.z, acc);
    acc = fmaf(a.w, b.w, acc);
    return acc;
}
__device__ __forceinline__ float4 add4(float4 a, float4 b)
{ return make_float4(a.x + b.x, a.y + b.y, a.z + b.z, a.w + b.w); }

__device__ __forceinline__ float warp_red(float a)
{
#pragma unroll
    for (int o = 16; o; o >>= 1) a += __shfl_xor_sync(0xffffffffu, a, o);
    return a;
}

// ---------------- fcA: 2048x8192 GEMV, K-split 4 ----------------
// grid = 6 * 256 * 4 = 6144 blocks, 256 threads (8 rows/block).
__global__ void __launch_bounds__(256) k_fcA(const float* __restrict__ W)
{
    __shared__ float4 sx[512];                // 2048-float chunk of ys
    const int bid   = blockIdx.x;
    const int s     = bid >> 10;              // / 1024
    const int rem   = bid & 1023;
    const int chunk = rem >> 8;               // / 256
    const int row   = (rem & 255) * 8 + (threadIdx.x >> 5);
    const int lane  = threadIdx.x & 31;

    const float4* __restrict__ xv = (const float4*)(g_ys + s * 8192 + chunk * 2048);
    for (int i = threadIdx.x; i < 512; i += 256) sx[i] = xv[i];
    __syncthreads();

    const float4* __restrict__ wv =
        (const float4*)(W + (size_t)(s * 2048 + row) * 8192 + chunk * 2048);

    float a0 = 0.f, a1 = 0.f, a2 = 0.f, a3 = 0.f;
#pragma unroll 2
    for (int t = 0; t < 4; t++) {
        const int b = t * 128 + lane;
        float4 w0 = wv[b], w1 = wv[b + 32], w2 = wv[b + 64], w3 = wv[b + 96];
        a0 = dot4(w0, sx[b], a0);
        a1 = dot4(w1, sx[b + 32], a1);
        a2 = dot4(w2, sx[b + 64], a2);
        a3 = dot4(w3, sx[b + 96], a3);
    }
    float a = warp_red((a0 + a1) + (a2 + a3));
    if (lane == 0) g_h1p[chunk][s * 2048 + row] = a;
}

// ---------------- fcB: 512x2048 GEMV, K-split 2; x = sum(fcA partials)+bA ----
__global__ void __launch_bounds__(256) k_fcB(const float* __restrict__ W,
                                             const float* __restrict__ bA)
{
    __shared__ float4 sx[256];                // 1024-float chunk of h1
    const int bid   = blockIdx.x;
    const int s     = bid >> 7;               // / 128
    const int rem   = bid & 127;
    const int chunk = rem >> 6;
    const int row   = (rem & 63) * 8 + (threadIdx.x >> 5);
    const int lane  = threadIdx.x & 31;

    const int xoff = (s * 2048 + chunk * 1024) >> 2;   // float4 offset
    {
        const float4* p0 = ((const float4*)g_h1p[0]) + xoff;
        const float4* p1 = ((const float4*)g_h1p[1]) + xoff;
        const float4* p2 = ((const float4*)g_h1p[2]) + xoff;
        const float4* p3 = ((const float4*)g_h1p[3]) + xoff;
        const float4* bb = ((const float4*)bA) + xoff;
        for (int i = threadIdx.x; i < 256; i += 256)
            sx[i] = add4(add4(add4(p0[i], p1[i]), add4(p2[i], p3[i])), bb[i]);
    }
    __syncthreads();

    const float4* __restrict__ wv =
        (const float4*)(W + (size_t)(s * 512 + row) * 2048 + chunk * 1024);

    float a0 = 0.f, a1 = 0.f, a2 = 0.f, a3 = 0.f;
#pragma unroll 2
    for (int t = 0; t < 2; t++) {
        const int b = t * 128 + lane;
        float4 w0 = wv[b], w1 = wv[b + 32], w2 = wv[b + 64], w3 = wv[b + 96];
        a0 = dot4(w0, sx[b], a0);
        a1 = dot4(w1, sx[b + 32], a1);
        a2 = dot4(w2, sx[b + 64], a2);
        a3 = dot4(w3, sx[b + 96], a3);
    }
    float a = warp_red((a0 + a1) + (a2 + a3));
    if (lane == 0) g_h2p[chunk][s * 512 + row] = a;
}

// ---------------- fcC: 512x512 GEMV; x = sum(fcB partials)+bB -------------
__global__ void __launch_bounds__(256) k_fcC(const float* __restrict__ W,
                                             const float* __restrict__ bB,
                                             const float* __restrict__ bC,
                                             float* __restrict__ out)
{
    __shared__ float4 sx[128];                // 512 floats of h2
    const int bid  = blockIdx.x;
    const int s    = bid >> 6;
    const int row  = (bid & 63) * 8 + (threadIdx.x >> 5);
    const int lane = threadIdx.x & 31;

    {
        const int xoff = (s * 512) >> 2;
        const float4* p0 = ((const float4*)g_h2p[0]) + xoff;
        const float4* p1 = ((const float4*)g_h2p[1]) + xoff;
        const float4* bb = ((const float4*)bB) + xoff;
        if (threadIdx.x < 128)
            sx[threadIdx.x] = add4(add4(p0[threadIdx.x], p1[threadIdx.x]), bb[threadIdx.x]);
    }
    __syncthreads();

    const float4* __restrict__ wv = (const float4*)(W + (size_t)(s * 512 + row) * 512);

    const int b = lane;
    float a0 = dot4(wv[b],      sx[b],      0.f);
    float a1 = dot4(wv[b + 32], sx[b + 32], 0.f);
    float a2 = dot4(wv[b + 64], sx[b + 64], 0.f);
    float a3 = dot4(wv[b + 96], sx[b + 96], 0.f);
    float a = warp_red((a0 + a1) + (a2 + a3));
    if (lane == 0) {
        float r = a + bC[s * 512 + row];
        g_w0[s * 512 + row] = r;
        out[s * 960 + row]  = r;
    }
}

// ---------------- tail: p1 -> p2 -> p3 fused, 6 blocks x 1024 thr ---------
__device__ __forceinline__ void tail_layer(const float* __restrict__ W,
                                           const float* __restrict__ bias,
                                           const float* __restrict__ xsm,
                                           float* __restrict__ ysm,
                                           float* __restrict__ out, int rows, int klen,
                                           int wid, int lane)
{
    const int k4 = klen >> 2;
    for (int row = wid; row < rows; row += 32) {
        const float4* wr = (const float4*)(W + (size_t)row * klen);
        const float4* xr = (const float4*)xsm;
        float a = 0.f;
        for (int i = lane; i < k4; i += 32) a = dot4(wr[i], xr[i], a);
        a = warp_red(a);
        if (lane == 0) {
            float r = a + bias[row];
            if (ysm) ysm[row] = r;
            out[row] = r;
        }
    }
}

__global__ void __launch_bounds__(1024) k_tail(
    const float* __restrict__ p1w, const float* __restrict__ p1b,
    const float* __restrict__ p2w, const float* __restrict__ p2b,
    const float* __restrict__ p3w, const float* __restrict__ p3b,
    float* __restrict__ out)
{
    const int s = blockIdx.x;
    const int wid = threadIdx.x >> 5;
    const int lane = threadIdx.x & 31;
    __shared__ float sw0[512], sw1[256], sw2[128];

    if (threadIdx.x < 512) sw0[threadIdx.x] = g_w0[s * 512 + threadIdx.x];
    __syncthreads();
    tail_layer(p1w, p1b, sw0, sw1, out + s * 960 + 512, 256, 512, wid, lane);
    __syncthreads();
    tail_layer(p2w, p2b, sw1, sw2, out + s * 960 + 768, 128, 256, wid, lane);
    __syncthreads();
    tail_layer(p3w, p3b, sw2, nullptr, out + s * 960 + 896, 64, 128, wid, lane);
}

// ---------------- launch ----------------
extern "C" void kernel_launch(void* const* d_in, const int* in_sizes, int n_in,
                              void* d_out, int out_size)
{
    const float* xs      = (const float*)d_in[0];
    const int*   parsing = (const int*)  d_in[1];
    const float* fcA_w   = (const float*)d_in[2];
    const float* fcA_b   = (const float*)d_in[3];
    const float* fcB_w   = (const float*)d_in[4];
    const float* fcB_b   = (const float*)d_in[5];
    const float* fcC_w   = (const float*)d_in[6];
    const float* fcC_b   = (const float*)d_in[7];
    const float* p1_w    = (const float*)d_in[8];
    const float* p1_b    = (const float*)d_in[9];
    const float* p2_w    = (const float*)d_in[10];
    const float* p2_b    = (const float*)d_in[11];
    const float* p3_w    = (const float*)d_in[12];
    const float* p3_b    = (const float*)d_in[13];
    float* out = (float*)d_out;

    k_mask<<<12, 256>>>(parsing);                    // #0
    k_bins<<<NSEG, 512>>>();                         // #1
    k_pool<<<NSEG * 128, 512>>>(xs);                 // #2
    k_fcA <<<NSEG * 256 * 4, 256>>>(fcA_w);          // #3  <- profiled
    k_fcB <<<NSEG * 64 * 2, 256>>>(fcB_w, fcA_b);
    k_fcC <<<NSEG * 64, 256>>>(fcC_w, fcB_b, fcC_b, out);
    k_tail<<<NSEG, 1024>>>(p1_w, p1_b, p2_w, p2_b, p3_w, p3_b, out);
}